// round 17
// baseline (speedup 1.0000x reference)
#include <cuda_runtime.h>
#include <cuda_bf16.h>
#include <cstdint>

// ---------------------------------------------------------------------------
// SINDy layer: out[b, c] = sum_t Theta(z[b])[t] * (Xi*mask)[t, c]
// B=65536, Z=32, terms = 6545 (padded to 6656).
//
// R15: dual-path build. The harness compiles a non-arch-specific (sm_103)
// pass where tcgen05 is illegal, so every tcgen05 instruction is guarded by
// __CUDA_ARCH_FEAT_SM103_ALL. The TC kernel and the FFMA2 kernels have
// complementary no-op bodies per pass; the host launches both, and whichever
// cubin the driver selects, exactly one path does the work:
//   sm_103a cubin: tcgen05 bf16-split GEMM  (target ~150-280 us)
//   sm_103  cubin: R13 persistent split-K FFMA2 (verified 674 us)
// ---------------------------------------------------------------------------

#if defined(__CUDA_ARCH_FEAT_SM103_ALL) || defined(__CUDA_ARCH_FEAT_SM100_ALL)
#define HAS_TC 1
#else
#define HAS_TC 0
#endif

#define ZDIM 32
#define NT 6545
#define NTP 6656
#define IDX_SAFE (32u | (32u << 8) | (32u << 16))

// ---- TC path constants ----
#define KCHUNK 64
#define TC_NCH 104                     // 104 * 64 = 6656
#define TC_THREADS 256
#define MTILE 128
#define TC_GRID 512                    // 65536 / 128
#define OFF_AH   0                     // A_hi 128x64 bf16 SW128 (16384)
#define OFF_AL   16384                 // A_lo (16384)
#define OFF_B    32768                 // 2 bufs x (B_hi 4096 + B_lo 4096)
#define OFF_ZT   49152                 // zT fp32 [33][128] (16896)
#define OFF_IDXS 66048                 // idx u32 [6656] (26624)
#define OFF_CTL  92672                 // [0]=tmem ptr, [8]=mbarrier
#define SMEM_TC  92736
#define MMA_IDESC 0x8080490u           // f32 accum, bf16 K-major, M=128, N=32

// ---- FFMA2 (R13) path constants ----
#define SLICES 8
#define TPS 832
#define FCHUNK 208
#define NITEMS 2048
#define FGRID 296
#define FTHREADS 128
#define FROWS 256
#define FOFF_XI0 0
#define FOFF_XI1 26624
#define FOFF_I0  53248
#define FOFF_I1  54112
#define FOFF_Z   54976
#define SMEM_FF  (54976 + 33792)       // 88768

// ---- device globals (legal scratch) ----
__device__ __align__(16) __nv_bfloat16 g_xiT_hi[ZDIM * NTP];      // TC: [n][k]
__device__ __align__(16) __nv_bfloat16 g_xiT_lo[ZDIM * NTP];
__device__ __align__(16) float    g_xi_eff[NTP * ZDIM];           // FF: [k][n]
__device__ __align__(16) unsigned g_idx[NTP];
__device__ __align__(16) float    g_part[SLICES * 65536 * ZDIM];  // FF: 64 MB

// SW128 desc base: layout=SW128, version=1 (Blackwell), SBO=64, LBO=1
static constexpr uint64_t DESC_BASE =
    (uint64_t(2) << 61) | (uint64_t(1) << 46) |
    (uint64_t(64) << 32) | (uint64_t(1) << 16);
#define MAKE_DESC(addr) (DESC_BASE | ((uint64_t)((addr) >> 4) & 0x3FFF))

// ---------------- common PTX helpers ----------------
__device__ __forceinline__ uint32_t smem_u32(const void* p) {
    uint32_t a;
    asm("{ .reg .u64 t; cvta.to.shared.u64 t, %1; cvt.u32.u64 %0, t; }"
        : "=r"(a) : "l"(p));
    return a;
}
#define CP_ASYNC16(dst_u32, src_ptr) \
    asm volatile("cp.async.cg.shared.global [%0], [%1], 16;" \
                 :: "r"(dst_u32), "l"(src_ptr) : "memory")
#define CP_COMMIT() asm volatile("cp.async.commit_group;" ::: "memory")
#define CP_WAIT(N)  asm volatile("cp.async.wait_group %0;" :: "n"(N) : "memory")

#define FMA2(d, a, b, c) \
    asm("fma.rn.f32x2 %0, %1, %2, %3;" : "=l"(d) : "l"(a), "l"(b), "l"(c))
#define MUL2(d, a, b) \
    asm("mul.rn.f32x2 %0, %1, %2;" : "=l"(d) : "l"(a), "l"(b))
#define PACK2(d, s) \
    asm("mov.b64 %0, {%1, %1};" : "=l"(d) : "r"(s))
#define SPLIT2(lo, hi, p) \
    asm("mov.b64 {%0, %1}, %2;" : "=r"(lo), "=r"(hi) : "l"(p))
#define UNPACK2(x, y, p) \
    asm("mov.b64 {%0, %1}, %2;" : "=f"(x), "=f"(y) : "l"(p))

// ---------------- idx table builder (shared, verified R13) -----------------
__device__ __forceinline__ void build_idx_block(int t) {
    if (t >= 64) return;
    if (t < 32) {
        int i = t;
        int pos = 33 + 32 * i - (i * (i - 1)) / 2;
        for (int j = i; j < 32; j++)
            g_idx[pos++] = (unsigned)i | ((unsigned)j << 8) | (32u << 16);
        int cpos = 561;
        for (int a = 0; a < i; a++) cpos += ((32 - a) * (33 - a)) / 2;
        for (int j = i; j < 32; j++)
            for (int k = j; k < 32; k++)
                g_idx[cpos++] = (unsigned)i | ((unsigned)j << 8) | ((unsigned)k << 16);
    } else if (t == 32) {
        g_idx[0] = IDX_SAFE;
        for (int k = 0; k < 32; k++)
            g_idx[1 + k] = (unsigned)k | (32u << 8) | (32u << 16);
    } else {
        for (int p = NT + (t - 33); p < NTP; p += 31)
            g_idx[p] = IDX_SAFE;
    }
}

// ---------------- prep (per-pass body) --------------------------------------
__global__ void prep_kernel(const float* __restrict__ Xi,
                            const float* __restrict__ mask) {
    if (blockIdx.x >= 832) { build_idx_block(threadIdx.x); return; }
    int i = blockIdx.x * 256 + threadIdx.x;
#if HAS_TC
    // i = n*NTP + k : transposed, premasked, bf16 hi/lo split
    int n = i / NTP, k = i - n * NTP;
    float v = 0.f;
    if (k < NT) v = Xi[k * ZDIM + n] * mask[k * ZDIM + n];
    __nv_bfloat16 h = __float2bfloat16(v);
    g_xiT_hi[i] = h;
    g_xiT_lo[i] = __float2bfloat16(v - __bfloat162float(h));
#else
    // row-major fp32 premask, zero-padded tail
    if (i < NTP * ZDIM)
        g_xi_eff[i] = (i < NT * ZDIM) ? Xi[i] * mask[i] : 0.f;
#endif
}

// ===========================================================================
// TC kernel (real body only in the sm_103a pass)
// ===========================================================================
#if HAS_TC
#define MBAR_INIT(a, n) \
    asm volatile("mbarrier.init.shared.b64 [%0], %1;" :: "r"(a), "r"(n) : "memory")
#define MBAR_WAIT(a, ph) do {                                                \
    asm volatile("{\n\t.reg .pred P;\n\tWL%=:\n\t"                           \
        "mbarrier.try_wait.parity.acquire.cta.shared::cta.b64 P, [%0], %1, 0x989680;\n\t" \
        "@!P bra WL%=;\n\t}" :: "r"(a), "r"(ph) : "memory");                 \
} while (0)
#define TC_FENCE_AFTER() asm volatile("tcgen05.fence::after_thread_sync;" ::: "memory")
#define FENCE_ASYNC()    asm volatile("fence.proxy.async;" ::: "memory")

__device__ __forceinline__ void mma_f16_ss(uint32_t d, uint64_t a_desc,
                                           uint64_t b_desc, bool acc) {
    uint32_t e = acc ? 1u : 0u;
    asm volatile(
        "{\n\t.reg .pred p;\n\tsetp.ne.u32 p, %5, 0;\n\t"
        "tcgen05.mma.cta_group::1.kind::f16 [%0], %1, %2, %3, {%4, %4, %4, %4}, p;\n\t}"
        :: "r"(d), "l"(a_desc), "l"(b_desc), "r"(MMA_IDESC), "r"(0u), "r"(e)
        : "memory");
}

#define STAGE_B(c) do {                                                      \
    int _b = (c) & 1;                                                        \
    int _n = tid >> 3, _q = tid & 7;                                         \
    uint32_t _off = (uint32_t)(_n * 128 + _q * 16);                          \
    _off ^= (_off >> 3) & 0x70;                                              \
    const __nv_bfloat16* _sh = g_xiT_hi + _n * NTP + (c) * KCHUNK + _q * 8;  \
    const __nv_bfloat16* _sl = g_xiT_lo + _n * NTP + (c) * KCHUNK + _q * 8;  \
    CP_ASYNC16(sbase + OFF_B + _b * 8192 + _off, _sh);                       \
    CP_ASYNC16(sbase + OFF_B + _b * 8192 + 4096 + _off, _sl);                \
    CP_COMMIT();                                                             \
} while (0)
#endif  // HAS_TC

__global__ void __launch_bounds__(TC_THREADS)
sindy_tc_kernel(const float* __restrict__ z, float* __restrict__ out) {
#if HAS_TC
    extern __shared__ __align__(16) char smem[];
    const int tid = threadIdx.x;
    const int cta = blockIdx.x;
    const uint32_t sbase = smem_u32(smem);
    const uint32_t mbar = sbase + OFF_CTL + 8;

    if (tid < 32) {
        asm volatile("tcgen05.alloc.cta_group::1.sync.aligned.shared::cta.b32 [%0], %1;"
                     :: "r"(sbase + OFF_CTL), "r"(128u) : "memory");
        asm volatile("tcgen05.relinquish_alloc_permit.cta_group::1.sync.aligned;");
    }
    if (tid == 0) MBAR_INIT(mbar, 1);

    STAGE_B(0);

    // zT[a][r] fp32 + sentinel row a=32 = 1.0
    {
        float* zt = (float*)(smem + OFF_ZT);
        if (tid < MTILE) {
            const float4* zr = (const float4*)z + ((size_t)cta * MTILE + tid) * 8;
            #pragma unroll
            for (int u = 0; u < 8; u++) {
                float4 v = zr[u];
                zt[(u * 4 + 0) * 128 + tid] = v.x;
                zt[(u * 4 + 1) * 128 + tid] = v.y;
                zt[(u * 4 + 2) * 128 + tid] = v.z;
                zt[(u * 4 + 3) * 128 + tid] = v.w;
            }
            zt[32 * 128 + tid] = 1.f;
        }
    }
    {
        unsigned* xs = (unsigned*)(smem + OFF_IDXS);
        for (int i = tid; i < NTP; i += TC_THREADS) xs[i] = g_idx[i];
    }
    __syncthreads();

    uint32_t tmem;
    asm volatile("ld.shared.b32 %0, [%1];" : "=r"(tmem) : "r"(sbase + OFF_CTL));

    const int row  = tid & 127;
    const int half = tid >> 7;
    const float* zTp = (const float*)(smem + OFF_ZT) + row;

    for (int c = 0; c < TC_NCH; c++) {
        const int buf = c & 1;

        // ---- theta-gen chunk c into registers (overlaps MMA(c-1)) ----
        unsigned hp[16], lp[16];
        {
            const uint2* ip = (const uint2*)((const unsigned*)(smem + OFF_IDXS)
                                             + c * KCHUNK + half * 32);
            unsigned prev = 0xFFFFFFFFu;
            float pair = 1.f;
            #pragma unroll
            for (int s = 0; s < 16; s++) {
                uint2 pp = ip[s];
                if ((pp.x ^ prev) & 0xFFFFu)
                    pair = zTp[(pp.x & 255u) << 7] * zTp[((pp.x >> 8) & 255u) << 7];
                float t0 = pair * zTp[(pp.x >> 16) << 7];
                prev = pp.x;
                if ((pp.y ^ prev) & 0xFFFFu)
                    pair = zTp[(pp.y & 255u) << 7] * zTp[((pp.y >> 8) & 255u) << 7];
                float t1 = pair * zTp[(pp.y >> 16) << 7];
                prev = pp.y;
                unsigned h;
                asm("cvt.rn.bf16x2.f32 %0, %1, %2;" : "=r"(h) : "f"(t1), "f"(t0));
                float f0 = __uint_as_float(h << 16);
                float f1 = __uint_as_float(h & 0xFFFF0000u);
                float l0 = t0 - f0, l1 = t1 - f1;
                unsigned l;
                asm("cvt.rn.bf16x2.f32 %0, %1, %2;" : "=r"(l) : "f"(l1), "f"(l0));
                hp[s] = h; lp[s] = l;
            }
        }

        // ---- wait MMA(c-1): A tile + B buf (c+1)&1 free ----
        if (c > 0) { MBAR_WAIT(mbar, (c - 1) & 1); TC_FENCE_AFTER(); }

        if (c + 1 < TC_NCH) { STAGE_B(c + 1); CP_WAIT(1); }
        else                { CP_WAIT(0); }

        // ---- store A tile (SW128) ----
        #pragma unroll
        for (int q = 0; q < 4; q++) {
            uint32_t off = (uint32_t)(row * 128 + half * 64 + q * 16);
            uint32_t sw = off ^ ((off >> 3) & 0x70);
            *(uint4*)(smem + OFF_AH + sw) =
                make_uint4(hp[4 * q], hp[4 * q + 1], hp[4 * q + 2], hp[4 * q + 3]);
            *(uint4*)(smem + OFF_AL + sw) =
                make_uint4(lp[4 * q], lp[4 * q + 1], lp[4 * q + 2], lp[4 * q + 3]);
        }

        FENCE_ASYNC();
        __syncthreads();

        if (tid == 0) {
            uint64_t ah = MAKE_DESC(sbase + OFF_AH);
            uint64_t al = MAKE_DESC(sbase + OFF_AL);
            uint64_t bh = MAKE_DESC(sbase + OFF_B + buf * 8192);
            uint64_t bl = MAKE_DESC(sbase + OFF_B + buf * 8192 + 4096);
            #pragma unroll
            for (int ks = 0; ks < 4; ks++) {
                mma_f16_ss(tmem, ah + ks * 2, bh + ks * 2, !(c == 0 && ks == 0));
                mma_f16_ss(tmem, ah + ks * 2, bl + ks * 2, true);
                mma_f16_ss(tmem, al + ks * 2, bh + ks * 2, true);
            }
            asm volatile(
                "tcgen05.commit.cta_group::1.mbarrier::arrive::one.shared::cluster.b64 [%0];"
                :: "r"(mbar) : "memory");
        }
        __syncthreads();
    }

    MBAR_WAIT(mbar, (TC_NCH - 1) & 1);
    TC_FENCE_AFTER();

    if (tid < 128) {
        uint32_t d[32];
        asm volatile(
            "tcgen05.ld.sync.aligned.32x32b.x32.b32 "
            "{%0,%1,%2,%3,%4,%5,%6,%7,%8,%9,%10,%11,%12,%13,%14,%15,"
            "%16,%17,%18,%19,%20,%21,%22,%23,%24,%25,%26,%27,%28,%29,%30,%31}, [%32];"
            : "=r"(d[0]), "=r"(d[1]), "=r"(d[2]), "=r"(d[3]), "=r"(d[4]),
              "=r"(d[5]), "=r"(d[6]), "=r"(d[7]), "=r"(d[8]), "=r"(d[9]),
              "=r"(d[10]), "=r"(d[11]), "=r"(d[12]), "=r"(d[13]), "=r"(d[14]),
              "=r"(d[15]), "=r"(d[16]), "=r"(d[17]), "=r"(d[18]), "=r"(d[19]),
              "=r"(d[20]), "=r"(d[21]), "=r"(d[22]), "=r"(d[23]), "=r"(d[24]),
              "=r"(d[25]), "=r"(d[26]), "=r"(d[27]), "=r"(d[28]), "=r"(d[29]),
              "=r"(d[30]), "=r"(d[31])
            : "r"(tmem));
        asm volatile("tcgen05.wait::ld.sync.aligned;" ::: "memory");

        int r = cta * MTILE + (tid >> 5) * 32 + (tid & 31);
        float4* o = (float4*)(out + (size_t)r * ZDIM);
        #pragma unroll
        for (int q = 0; q < 8; q++)
            o[q] = make_float4(__uint_as_float(d[4 * q]),
                               __uint_as_float(d[4 * q + 1]),
                               __uint_as_float(d[4 * q + 2]),
                               __uint_as_float(d[4 * q + 3]));
    }

    __syncthreads();
    if (tid < 32)
        asm volatile("tcgen05.dealloc.cta_group::1.sync.aligned.b32 %0, %1;"
                     :: "r"(tmem), "r"(128u));
#else
    (void)z; (void)out;   // no-op in the sm_103 cubin
#endif
}

// ===========================================================================
// FFMA2 fallback (verified R13; real body only in the non-a pass)
// ===========================================================================
#if !HAS_TC
#define FSTAGE(kb, ci) do {                                                  \
    int _buf = (ci) & 1;                                                     \
    uint32_t _dx = sbase + (_buf ? (uint32_t)FOFF_XI1 : (uint32_t)FOFF_XI0); \
    uint32_t _di = sbase + (_buf ? (uint32_t)FOFF_I1  : (uint32_t)FOFF_I0);  \
    const float4* _xs = (const float4*)g_xi_eff                              \
                        + ((size_t)(kb) + (size_t)(ci) * FCHUNK) * 8;        \
    _Pragma("unroll")                                                        \
    for (int _u = 0; _u < 13; _u++) {                                        \
        int _q = _u * FTHREADS + tid;                                        \
        CP_ASYNC16(_dx + 16u * (uint32_t)_q, _xs + _q);                      \
    }                                                                        \
    if (tid < 52) {                                                          \
        const float4* _is = (const float4*)(g_idx + (kb) + (ci) * FCHUNK)    \
                            + tid;                                           \
        CP_ASYNC16(_di + 16u * (uint32_t)tid, _is);                          \
    }                                                                        \
    if (tid == 64)                                                           \
        *(unsigned*)(smem + (_buf ? FOFF_I1 : FOFF_I0) + FCHUNK * 4) = IDX_SAFE; \
    CP_COMMIT();                                                             \
} while (0)
#endif

__global__ void __launch_bounds__(FTHREADS, 2)
sindy_ffma_kernel(const float* __restrict__ z) {
#if !HAS_TC
    extern __shared__ __align__(16) char smem[];
    const int tid = threadIdx.x;
    const uint32_t sbase = smem_u32(smem);

    ((float2*)(smem + FOFF_Z))[32 * 128 + tid] = make_float2(1.f, 1.f);
    const unsigned long long* zz =
        (const unsigned long long*)(smem + FOFF_Z) + tid;

    for (int it = blockIdx.x; it < NITEMS; it += FGRID) {
        const int r = it & 255;
        const int s = it >> 8;
        const int kb = s * TPS;

        FSTAGE(kb, 0);
        FSTAGE(kb, 1);

        {
            float2* zp = (float2*)(smem + FOFF_Z);
            const float4* r0 = (const float4*)z + ((size_t)r * FROWS + tid) * 8;
            const float4* r1 = r0 + 128 * 8;
            #pragma unroll
            for (int u = 0; u < 8; u++) {
                float4 a = r0[u];
                float4 b = r1[u];
                zp[(u * 4 + 0) * 128 + tid] = make_float2(a.x, b.x);
                zp[(u * 4 + 1) * 128 + tid] = make_float2(a.y, b.y);
                zp[(u * 4 + 2) * 128 + tid] = make_float2(a.z, b.z);
                zp[(u * 4 + 3) * 128 + tid] = make_float2(a.w, b.w);
            }
        }

        CP_WAIT(1);
        __syncthreads();

        unsigned long long acc0[16], acc1[16];
        #pragma unroll
        for (int m = 0; m < 16; m++) { acc0[m] = 0ull; acc1[m] = 0ull; }

        for (int c = 0; c < 4; c++) {
            const int buf = c & 1;
            const ulonglong2* xb =
                (const ulonglong2*)(smem + (buf ? FOFF_XI1 : FOFF_XI0));
            const unsigned* idxp =
                (const unsigned*)(smem + (buf ? FOFF_I1 : FOFF_I0));

            unsigned p0 = idxp[0];
            unsigned long long za = zz[(p0 & 255u) << 7];
            unsigned long long zb = zz[((p0 >> 8) & 255u) << 7];
            unsigned long long zc = zz[(p0 >> 16) << 7];

            #pragma unroll 2
            for (int t = 0; t < FCHUNK; t++) {
                unsigned long long th;
                MUL2(th, za, zb);
                MUL2(th, th, zc);

                unsigned pn = idxp[t + 1];
                za = zz[(pn & 255u) << 7];
                zb = zz[((pn >> 8) & 255u) << 7];
                zc = zz[(pn >> 16) << 7];

                unsigned lo, hi;
                SPLIT2(lo, hi, th);
                unsigned long long t00, t11;
                PACK2(t00, lo);
                PACK2(t11, hi);

                const ulonglong2* xt = xb + t * 8;
                ulonglong2 q0 = xt[0], q1 = xt[1], q2 = xt[2], q3 = xt[3];
                ulonglong2 q4 = xt[4], q5 = xt[5], q6 = xt[6], q7 = xt[7];

                FMA2(acc0[ 0], t00, q0.x, acc0[ 0]); FMA2(acc1[ 0], t11, q0.x, acc1[ 0]);
                FMA2(acc0[ 1], t00, q0.y, acc0[ 1]); FMA2(acc1[ 1], t11, q0.y, acc1[ 1]);
                FMA2(acc0[ 2], t00, q1.x, acc0[ 2]); FMA2(acc1[ 2], t11, q1.x, acc1[ 2]);
                FMA2(acc0[ 3], t00, q1.y, acc0[ 3]); FMA2(acc1[ 3], t11, q1.y, acc1[ 3]);
                FMA2(acc0[ 4], t00, q2.x, acc0[ 4]); FMA2(acc1[ 4], t11, q2.x, acc1[ 4]);
                FMA2(acc0[ 5], t00, q2.y, acc0[ 5]); FMA2(acc1[ 5], t11, q2.y, acc1[ 5]);
                FMA2(acc0[ 6], t00, q3.x, acc0[ 6]); FMA2(acc1[ 6], t11, q3.x, acc1[ 6]);
                FMA2(acc0[ 7], t00, q3.y, acc0[ 7]); FMA2(acc1[ 7], t11, q3.y, acc1[ 7]);
                FMA2(acc0[ 8], t00, q4.x, acc0[ 8]); FMA2(acc1[ 8], t11, q4.x, acc1[ 8]);
                FMA2(acc0[ 9], t00, q4.y, acc0[ 9]); FMA2(acc1[ 9], t11, q4.y, acc1[ 9]);
                FMA2(acc0[10], t00, q5.x, acc0[10]); FMA2(acc1[10], t11, q5.x, acc1[10]);
                FMA2(acc0[11], t00, q5.y, acc0[11]); FMA2(acc1[11], t11, q5.y, acc1[11]);
                FMA2(acc0[12], t00, q6.x, acc0[12]); FMA2(acc1[12], t11, q6.x, acc1[12]);
                FMA2(acc0[13], t00, q6.y, acc0[13]); FMA2(acc1[13], t11, q6.y, acc1[13]);
                FMA2(acc0[14], t00, q7.x, acc0[14]); FMA2(acc1[14], t11, q7.x, acc1[14]);
                FMA2(acc0[15], t00, q7.y, acc0[15]); FMA2(acc1[15], t11, q7.y, acc1[15]);
            }

            __syncthreads();
            if (c < 2)       { FSTAGE(kb, c + 2); CP_WAIT(1); }
            else if (c == 2) { CP_WAIT(0); }
            __syncthreads();
        }

        size_t row0 = (size_t)r * FROWS + tid;
        float* gp = g_part + ((size_t)s << 21);
        float4* o0 = (float4*)(gp + row0 * ZDIM);
        float4* o1 = (float4*)(gp + (row0 + 128) * ZDIM);
        #pragma unroll
        for (int q = 0; q < 8; q++) {
            float4 v;
            UNPACK2(v.x, v.y, acc0[2 * q]);
            UNPACK2(v.z, v.w, acc0[2 * q + 1]);
            o0[q] = v;
        }
        #pragma unroll
        for (int q = 0; q < 8; q++) {
            float4 v;
            UNPACK2(v.x, v.y, acc1[2 * q]);
            UNPACK2(v.z, v.w, acc1[2 * q + 1]);
            o1[q] = v;
        }
    }
#else
    (void)z;   // no-op in the sm_103a cubin
#endif
}

__global__ void reduce_kernel(float* __restrict__ out) {
#if !HAS_TC
    int q = blockIdx.x * blockDim.x + threadIdx.x;
    const float4* p = (const float4*)g_part;
    float4 a = p[q];
    #pragma unroll
    for (int s = 1; s < SLICES; s++) {
        float4 b = p[(size_t)s * 524288 + q];
        a.x += b.x; a.y += b.y; a.z += b.z; a.w += b.w;
    }
    ((float4*)out)[q] = a;
#else
    (void)out;   // no-op in the sm_103a cubin (TC kernel wrote out directly)
#endif
}

// ---------------- launch ----------------------------------------------------
extern "C" void kernel_launch(void* const* d_in, const int* in_sizes, int n_in,
                              void* d_out, int out_size) {
    (void)in_sizes; (void)n_in; (void)out_size;
    const float* z    = (const float*)d_in[0];  // [65536, 32]
    const float* Xi   = (const float*)d_in[1];  // [6545, 32]
    const float* mask = (const float*)d_in[2];  // [6545, 32]
    float* out = (float*)d_out;                 // [65536, 32]

    prep_kernel<<<833, 256>>>(Xi, mask);

    (void)cudaFuncSetAttribute(sindy_tc_kernel,
                               cudaFuncAttributeMaxDynamicSharedMemorySize,
                               SMEM_TC);
    (void)cudaFuncSetAttribute(sindy_ffma_kernel,
                               cudaFuncAttributeMaxDynamicSharedMemorySize,
                               SMEM_FF);

    // Complementary no-ops: exactly one of these does the work, depending on
    // which cubin (sm_103a vs sm_103) the driver selected.
    sindy_tc_kernel<<<TC_GRID, TC_THREADS, SMEM_TC>>>(z, out);
    sindy_ffma_kernel<<<FGRID, FTHREADS, SMEM_FF>>>(z);
    reduce_kernel<<<2048, 256>>>(out);
}